// round 8
// baseline (speedup 1.0000x reference)
#include <cuda_runtime.h>
#include <cstdint>

#define VOCAB 50257
#define EMBED 128
#define BATCH 64
#define NSENT 50
#define TC 20
#define TQ 20
#define NHOPS 3

// Scratch (device global — no allocation allowed)
__device__ float g_u[BATCH * EMBED];
__device__ float g_m[BATCH * NSENT * EMBED];
__device__ float g_c[BATCH * NSENT * EMBED];

// ---------------------------------------------------------------------------
// Kernel 1: embedding sums. One WARP per sentence (or question).
// ---------------------------------------------------------------------------
__global__ void __launch_bounds__(128) embed_kernel(
        const int* __restrict__ stories,
        const int* __restrict__ questions,
        const int* __restrict__ masks,
        const float* __restrict__ WA,
        const float* __restrict__ WB,
        const float* __restrict__ WC,
        const float* __restrict__ WAT,
        const float* __restrict__ WCT) {
    int gwarp = (blockIdx.x * blockDim.x + threadIdx.x) >> 5;
    int lane = threadIdx.x & 31;

    if (gwarp < BATCH * NSENT) {
        int s = gwarp % NSENT;
        int mytok = (lane < TC) ? stories[gwarp * TC + lane] : 0;
        int mymsk = (lane < TC) ? masks[gwarp * TC + lane] : 1;
        unsigned ball = __ballot_sync(0xffffffffu, (lane < TC) && (mymsk == 0));
        int te = (ball != 0u) ? (s + 1) : 0;

        float4 ma = *(const float4*)&WAT[te * EMBED + lane * 4];
        float4 ca = *(const float4*)&WCT[te * EMBED + lane * 4];
#pragma unroll
        for (int t = 0; t < TC; t++) {
            int tk = __shfl_sync(0xffffffffu, mytok, t);
            float4 a = *(const float4*)&WA[(size_t)tk * EMBED + lane * 4];
            float4 c = *(const float4*)&WC[(size_t)tk * EMBED + lane * 4];
            ma.x += a.x; ma.y += a.y; ma.z += a.z; ma.w += a.w;
            ca.x += c.x; ca.y += c.y; ca.z += c.z; ca.w += c.w;
        }
        *(float4*)&g_m[(size_t)gwarp * EMBED + lane * 4] = ma;
        *(float4*)&g_c[(size_t)gwarp * EMBED + lane * 4] = ca;
    } else if (gwarp < BATCH * NSENT + BATCH) {
        int b = gwarp - BATCH * NSENT;
        int myq = (lane < TQ) ? questions[b * TQ + lane] : 0;
        float4 u = make_float4(0.f, 0.f, 0.f, 0.f);
#pragma unroll
        for (int t = 0; t < TQ; t++) {
            int tk = __shfl_sync(0xffffffffu, myq, t);
            float4 a = *(const float4*)&WB[(size_t)tk * EMBED + lane * 4];
            u.x += a.x; u.y += a.y; u.z += a.z; u.w += a.w;
        }
        *(float4*)&g_u[b * EMBED + lane * 4] = u;
    }
}

// ---------------------------------------------------------------------------
// Kernel 2: 3 attention hops. One block per batch row, 128 threads.
// ---------------------------------------------------------------------------
__global__ void hops_kernel() {
    int b = blockIdx.x;
    int tid = threadIdx.x;
    int w = tid >> 5, lane = tid & 31;
    __shared__ float u_s[EMBED];
    __shared__ float sc[64];
    u_s[tid] = g_u[b * EMBED + tid];
    __syncthreads();
    for (int hop = 0; hop < NHOPS; hop++) {
        float4 uv = *(const float4*)&u_s[lane * 4];
        for (int n = w; n < NSENT; n += 4) {
            float4 mv = *(const float4*)&g_m[((size_t)(b * NSENT + n)) * EMBED + lane * 4];
            float p = mv.x * uv.x + mv.y * uv.y + mv.z * uv.z + mv.w * uv.w;
#pragma unroll
            for (int o = 16; o > 0; o >>= 1) p += __shfl_xor_sync(0xffffffffu, p, o);
            if (lane == 0) sc[n] = p;
        }
        __syncthreads();
        if (w == 0) {
            float v0 = (lane < NSENT) ? sc[lane] : -1e30f;
            float v1 = (lane + 32 < NSENT) ? sc[lane + 32] : -1e30f;
            float mx = fmaxf(v0, v1);
#pragma unroll
            for (int o = 16; o > 0; o >>= 1) mx = fmaxf(mx, __shfl_xor_sync(0xffffffffu, mx, o));
            float e0 = (lane < NSENT) ? expf(v0 - mx) : 0.f;
            float e1 = (lane + 32 < NSENT) ? expf(v1 - mx) : 0.f;
            float s = e0 + e1;
#pragma unroll
            for (int o = 16; o > 0; o >>= 1) s += __shfl_xor_sync(0xffffffffu, s, o);
            float inv = 1.f / s;
            if (lane < NSENT) sc[lane] = e0 * inv;
            if (lane + 32 < NSENT) sc[lane + 32] = e1 * inv;
        }
        __syncthreads();
        float o_acc = 0.f;
#pragma unroll 10
        for (int n = 0; n < NSENT; n++)
            o_acc += g_c[((size_t)(b * NSENT + n)) * EMBED + tid] * sc[n];
        u_s[tid] += o_acc;
        __syncthreads();
    }
    g_u[b * EMBED + tid] = u_s[tid];
}

// ---------------------------------------------------------------------------
// Kernel 3: logits via warp-level tf32 mma.sync (m16n8k8, fp32 accumulate).
// 256 threads/CTA, 8 warps; per warp: 16 vocab rows x 64 batch (8 n-tiles).
// B = u staged tf32 in smem (pad 132 -> conflict-free frag loads).
// A = W fragments streamed from gmem with one-step software pipeline.
// ---------------------------------------------------------------------------
__device__ __forceinline__ uint32_t tf32b(float x) {
    float r;
    asm("cvt.rna.tf32.f32 %0, %1;" : "=f"(r) : "f"(x));
    return __float_as_uint(r);
}
__device__ __forceinline__ void mma_tf32(float* c, const uint32_t* a,
                                         uint32_t b0, uint32_t b1) {
    asm volatile(
        "mma.sync.aligned.m16n8k8.row.col.f32.tf32.tf32.f32 "
        "{%0,%1,%2,%3}, {%4,%5,%6,%7}, {%8,%9}, {%0,%1,%2,%3};"
        : "+f"(c[0]), "+f"(c[1]), "+f"(c[2]), "+f"(c[3])
        : "r"(a[0]), "r"(a[1]), "r"(a[2]), "r"(a[3]), "r"(b0), "r"(b1));
}

__global__ void __launch_bounds__(256) logits_mma_kernel(
        const float* __restrict__ W,
        const float* __restrict__ bias,
        float* __restrict__ out) {
    __shared__ uint32_t us[64][132];  // u in tf32 bits, padded row

    int tid = threadIdx.x;
    int wid = tid >> 5, lane = tid & 31;
    int gid = lane >> 2, tig = lane & 3;

    // ---- stage u -> tf32 smem ----
    for (int e = tid; e < 64 * 32; e += 256) {
        int row = e >> 5, q = e & 31;
        float4 v = *(const float4*)(g_u + row * EMBED + q * 4);
        us[row][q * 4 + 0] = tf32b(v.x);
        us[row][q * 4 + 1] = tf32b(v.y);
        us[row][q * 4 + 2] = tf32b(v.z);
        us[row][q * 4 + 3] = tf32b(v.w);
    }
    __syncthreads();

    int rbase = blockIdx.x * 128 + wid * 16;
    int rlo = rbase + gid;
    int rhi = rlo + 8;
    if (rlo > VOCAB - 1) rlo = VOCAB - 1;
    if (rhi > VOCAB - 1) rhi = VOCAB - 1;
    const float* wlo = W + (size_t)rlo * EMBED;
    const float* whi = W + (size_t)rhi * EMBED;

    float acc[8][4];
#pragma unroll
    for (int j = 0; j < 8; j++)
#pragma unroll
        for (int q = 0; q < 4; q++) acc[j][q] = 0.f;

    // software-pipelined A fragments
    float f0 = __ldg(wlo + tig);
    float f1 = __ldg(whi + tig);
    float f2 = __ldg(wlo + tig + 4);
    float f3 = __ldg(whi + tig + 4);

#pragma unroll
    for (int s = 0; s < 16; s++) {
        uint32_t a[4];
        a[0] = tf32b(f0);
        a[1] = tf32b(f1);
        a[2] = tf32b(f2);
        a[3] = tf32b(f3);
        if (s < 15) {
            int kn = (s + 1) * 8 + tig;
            f0 = __ldg(wlo + kn);
            f1 = __ldg(whi + kn);
            f2 = __ldg(wlo + kn + 4);
            f3 = __ldg(whi + kn + 4);
        }
        int k0 = s * 8 + tig;
#pragma unroll
        for (int j = 0; j < 8; j++) {
            uint32_t b0 = us[j * 8 + gid][k0];
            uint32_t b1 = us[j * 8 + gid][k0 + 4];
            mma_tf32(acc[j], a, b0, b1);
        }
    }

    // ---- epilogue: +bias, scalar stores (out is [batch][vocab]) ----
    int r_lo = rbase + gid;
    int r_hi = r_lo + 8;
    bool vlo = (r_lo < VOCAB), vhi = (r_hi < VOCAB);
    float blo = vlo ? bias[r_lo] : 0.f;
    float bhi = vhi ? bias[r_hi] : 0.f;
#pragma unroll
    for (int j = 0; j < 8; j++) {
        int n0 = j * 8 + 2 * tig;
        int n1 = n0 + 1;
        if (vlo) {
            out[(size_t)n0 * VOCAB + r_lo] = acc[j][0] + blo;
            out[(size_t)n1 * VOCAB + r_lo] = acc[j][1] + blo;
        }
        if (vhi) {
            out[(size_t)n0 * VOCAB + r_hi] = acc[j][2] + bhi;
            out[(size_t)n1 * VOCAB + r_hi] = acc[j][3] + bhi;
        }
    }
}

extern "C" void kernel_launch(void* const* d_in, const int* in_sizes, int n_in,
                              void* d_out, int out_size) {
    const int* stories = (const int*)d_in[0];
    const int* questions = (const int*)d_in[1];
    const int* masks = (const int*)d_in[2];
    const float* WA = (const float*)d_in[3];
    const float* WB = (const float*)d_in[4];
    const float* WC = (const float*)d_in[5];
    const float* WAT = (const float*)d_in[6];
    const float* WCT = (const float*)d_in[7];
    const float* Wlin = (const float*)d_in[8];
    const float* blin = (const float*)d_in[9];
    float* out = (float*)d_out;

    int total_warps = BATCH * NSENT + BATCH;
    int embed_blocks = (total_warps * 32 + 127) / 128;
    embed_kernel<<<embed_blocks, 128>>>(stories, questions, masks, WA, WB, WC, WAT, WCT);
    hops_kernel<<<BATCH, EMBED>>>();

    int nblk = (VOCAB + 127) / 128;  // 393
    logits_mma_kernel<<<nblk, 256>>>(Wlin, blin, out);
}

// round 9
// speedup vs baseline: 1.0645x; 1.0645x over previous
#include <cuda_runtime.h>
#include <cstdint>

#define VOCAB 50257
#define EMBED 128
#define BATCH 64
#define NSENT 50
#define TC 20
#define TQ 20
#define NHOPS 3

// Scratch (device global — no allocation allowed)
__device__ float g_u[BATCH * EMBED];
__device__ float g_m[BATCH * NSENT * EMBED];
__device__ float g_c[BATCH * NSENT * EMBED];

// ---------------------------------------------------------------------------
// Kernel 1: embedding sums. TWO warps per sentence (m-warp / c-warp) to double
// per-SM memory-level parallelism; one warp per question.
// ---------------------------------------------------------------------------
__global__ void __launch_bounds__(128) embed_kernel(
        const int* __restrict__ stories,
        const int* __restrict__ questions,
        const int* __restrict__ masks,
        const float* __restrict__ WA,
        const float* __restrict__ WB,
        const float* __restrict__ WC,
        const float* __restrict__ WAT,
        const float* __restrict__ WCT) {
    int gwarp = (blockIdx.x * blockDim.x + threadIdx.x) >> 5;
    int lane = threadIdx.x & 31;

    if (gwarp < 2 * BATCH * NSENT) {
        int sent = gwarp >> 1;          // sentence index in [0, B*NSENT)
        int half = gwarp & 1;           // 0 = m (WA/WAT), 1 = c (WC/WCT)
        int s = sent % NSENT;
        int mytok = (lane < TC) ? stories[sent * TC + lane] : 0;
        int mymsk = (lane < TC) ? masks[sent * TC + lane] : 1;
        unsigned ball = __ballot_sync(0xffffffffu, (lane < TC) && (mymsk == 0));
        int te = (ball != 0u) ? (s + 1) : 0;

        const float* tbl = half ? WC : WA;
        const float* ttbl = half ? WCT : WAT;
        float4 acc = *(const float4*)&ttbl[te * EMBED + lane * 4];
#pragma unroll
        for (int t = 0; t < TC; t++) {
            int tk = __shfl_sync(0xffffffffu, mytok, t);
            float4 a = *(const float4*)&tbl[(size_t)tk * EMBED + lane * 4];
            acc.x += a.x; acc.y += a.y; acc.z += a.z; acc.w += a.w;
        }
        float* dst = half ? g_c : g_m;
        *(float4*)&dst[(size_t)sent * EMBED + lane * 4] = acc;
    } else if (gwarp < 2 * BATCH * NSENT + BATCH) {
        int b = gwarp - 2 * BATCH * NSENT;
        int myq = (lane < TQ) ? questions[b * TQ + lane] : 0;
        float4 u = make_float4(0.f, 0.f, 0.f, 0.f);
#pragma unroll
        for (int t = 0; t < TQ; t++) {
            int tk = __shfl_sync(0xffffffffu, myq, t);
            float4 a = *(const float4*)&WB[(size_t)tk * EMBED + lane * 4];
            u.x += a.x; u.y += a.y; u.z += a.z; u.w += a.w;
        }
        *(float4*)&g_u[b * EMBED + lane * 4] = u;
    }
}

// ---------------------------------------------------------------------------
// Kernel 2: 3 attention hops. One block per batch row, 128 threads.
// ---------------------------------------------------------------------------
__global__ void hops_kernel() {
    int b = blockIdx.x;
    int tid = threadIdx.x;
    int w = tid >> 5, lane = tid & 31;
    __shared__ float u_s[EMBED];
    __shared__ float sc[64];
    u_s[tid] = g_u[b * EMBED + tid];
    __syncthreads();
    for (int hop = 0; hop < NHOPS; hop++) {
        float4 uv = *(const float4*)&u_s[lane * 4];
        for (int n = w; n < NSENT; n += 4) {
            float4 mv = *(const float4*)&g_m[((size_t)(b * NSENT + n)) * EMBED + lane * 4];
            float p = mv.x * uv.x + mv.y * uv.y + mv.z * uv.z + mv.w * uv.w;
#pragma unroll
            for (int o = 16; o > 0; o >>= 1) p += __shfl_xor_sync(0xffffffffu, p, o);
            if (lane == 0) sc[n] = p;
        }
        __syncthreads();
        if (w == 0) {
            float v0 = (lane < NSENT) ? sc[lane] : -1e30f;
            float v1 = (lane + 32 < NSENT) ? sc[lane + 32] : -1e30f;
            float mx = fmaxf(v0, v1);
#pragma unroll
            for (int o = 16; o > 0; o >>= 1) mx = fmaxf(mx, __shfl_xor_sync(0xffffffffu, mx, o));
            float e0 = (lane < NSENT) ? expf(v0 - mx) : 0.f;
            float e1 = (lane + 32 < NSENT) ? expf(v1 - mx) : 0.f;
            float s = e0 + e1;
#pragma unroll
            for (int o = 16; o > 0; o >>= 1) s += __shfl_xor_sync(0xffffffffu, s, o);
            float inv = 1.f / s;
            if (lane < NSENT) sc[lane] = e0 * inv;
            if (lane + 32 < NSENT) sc[lane + 32] = e1 * inv;
        }
        __syncthreads();
        float o_acc = 0.f;
#pragma unroll 10
        for (int n = 0; n < NSENT; n++)
            o_acc += g_c[((size_t)(b * NSENT + n)) * EMBED + tid] * sc[n];
        u_s[tid] += o_acc;
        __syncthreads();
    }
    g_u[b * EMBED + tid] = u_s[tid];
}

// ---------------------------------------------------------------------------
// Kernel 3: logits via warp-level tf32 mma.sync (m16n8k8, fp32 accumulate).
// 256 threads/CTA, 8 warps; per warp: 16 vocab rows x 64 batch (8 n-tiles).
// BOTH operands staged in padded smem (132 words/row -> conflict-free LDS):
//   us[64][132]  = u (tf32), ws[128][132] = W tile (tf32), coalesced LDG.128.
// DRAM traffic drops to compulsory 64KB/CTA (fixes 50% sector waste of R8).
// ---------------------------------------------------------------------------
__device__ __forceinline__ uint32_t tf32b(float x) {
    float r;
    asm("cvt.rna.tf32.f32 %0, %1;" : "=f"(r) : "f"(x));
    return __float_as_uint(r);
}
__device__ __forceinline__ void mma_tf32(float* c, const uint32_t* a,
                                         uint32_t b0, uint32_t b1) {
    asm volatile(
        "mma.sync.aligned.m16n8k8.row.col.f32.tf32.tf32.f32 "
        "{%0,%1,%2,%3}, {%4,%5,%6,%7}, {%8,%9}, {%0,%1,%2,%3};"
        : "+f"(c[0]), "+f"(c[1]), "+f"(c[2]), "+f"(c[3])
        : "r"(a[0]), "r"(a[1]), "r"(a[2]), "r"(a[3]), "r"(b0), "r"(b1));
}

#define LPAD 132
#define LG_SMEM_BYTES ((64 + 128) * LPAD * 4)

__global__ void __launch_bounds__(256) logits_mma_kernel(
        const float* __restrict__ W,
        const float* __restrict__ bias,
        float* __restrict__ out) {
    extern __shared__ uint32_t sh[];
    uint32_t (*us)[LPAD] = (uint32_t(*)[LPAD])sh;              // 64 rows
    uint32_t (*ws)[LPAD] = (uint32_t(*)[LPAD])(sh + 64 * LPAD); // 128 rows

    int tid = threadIdx.x;
    int wid = tid >> 5, lane = tid & 31;
    int gid = lane >> 2, tig = lane & 3;
    int row0 = blockIdx.x * 128;

    // ---- stage u -> tf32 smem (64 x 128) ----
#pragma unroll
    for (int i = 0; i < 8; i++) {
        int q = tid + 256 * i;             // quad index: 64*32
        int row = q >> 5, kq = q & 31;
        float4 v = *(const float4*)(g_u + row * EMBED + kq * 4);
        us[row][kq * 4 + 0] = tf32b(v.x);
        us[row][kq * 4 + 1] = tf32b(v.y);
        us[row][kq * 4 + 2] = tf32b(v.z);
        us[row][kq * 4 + 3] = tf32b(v.w);
    }
    // ---- stage W tile -> tf32 smem (128 x 128), coalesced LDG.128 ----
#pragma unroll
    for (int i = 0; i < 16; i++) {
        int q = tid + 256 * i;             // quad index: 128*32
        int row = q >> 5, kq = q & 31;
        int grow = row0 + row;
        if (grow > VOCAB - 1) grow = VOCAB - 1;
        float4 v = *(const float4*)(W + (size_t)grow * EMBED + kq * 4);
        ws[row][kq * 4 + 0] = tf32b(v.x);
        ws[row][kq * 4 + 1] = tf32b(v.y);
        ws[row][kq * 4 + 2] = tf32b(v.z);
        ws[row][kq * 4 + 3] = tf32b(v.w);
    }
    __syncthreads();

    int rl = wid * 16 + gid;   // local W row for a0/a2
    int rh = rl + 8;           // local W row for a1/a3

    float acc[8][4];
#pragma unroll
    for (int j = 0; j < 8; j++)
#pragma unroll
        for (int q = 0; q < 4; q++) acc[j][q] = 0.f;

#pragma unroll
    for (int s = 0; s < 16; s++) {
        int k0 = s * 8 + tig;
        uint32_t a[4];
        a[0] = ws[rl][k0];
        a[1] = ws[rh][k0];
        a[2] = ws[rl][k0 + 4];
        a[3] = ws[rh][k0 + 4];
#pragma unroll
        for (int j = 0; j < 8; j++) {
            uint32_t b0 = us[j * 8 + gid][k0];
            uint32_t b1 = us[j * 8 + gid][k0 + 4];
            mma_tf32(acc[j], a, b0, b1);
        }
    }

    // ---- epilogue: +bias, scalar stores (out is [batch][vocab]) ----
    int r_lo = row0 + rl;
    int r_hi = row0 + rh;
    bool vlo = (r_lo < VOCAB), vhi = (r_hi < VOCAB);
    float blo = vlo ? __ldg(bias + r_lo) : 0.f;
    float bhi = vhi ? __ldg(bias + r_hi) : 0.f;
#pragma unroll
    for (int j = 0; j < 8; j++) {
        int n0 = j * 8 + 2 * tig;
        int n1 = n0 + 1;
        if (vlo) {
            out[(size_t)n0 * VOCAB + r_lo] = acc[j][0] + blo;
            out[(size_t)n1 * VOCAB + r_lo] = acc[j][1] + blo;
        }
        if (vhi) {
            out[(size_t)n0 * VOCAB + r_hi] = acc[j][2] + bhi;
            out[(size_t)n1 * VOCAB + r_hi] = acc[j][3] + bhi;
        }
    }
}

extern "C" void kernel_launch(void* const* d_in, const int* in_sizes, int n_in,
                              void* d_out, int out_size) {
    const int* stories = (const int*)d_in[0];
    const int* questions = (const int*)d_in[1];
    const int* masks = (const int*)d_in[2];
    const float* WA = (const float*)d_in[3];
    const float* WB = (const float*)d_in[4];
    const float* WC = (const float*)d_in[5];
    const float* WAT = (const float*)d_in[6];
    const float* WCT = (const float*)d_in[7];
    const float* Wlin = (const float*)d_in[8];
    const float* blin = (const float*)d_in[9];
    float* out = (float*)d_out;

    // 2 warps per sentence + 1 per question = 6464 warps -> 1616 blocks
    int total_warps = 2 * BATCH * NSENT + BATCH;
    int embed_blocks = (total_warps * 32 + 127) / 128;
    embed_kernel<<<embed_blocks, 128>>>(stories, questions, masks, WA, WB, WC, WAT, WCT);
    hops_kernel<<<BATCH, EMBED>>>();

    cudaFuncSetAttribute(logits_mma_kernel,
                         cudaFuncAttributeMaxDynamicSharedMemorySize, LG_SMEM_BYTES);
    int nblk = (VOCAB + 127) / 128;  // 393
    logits_mma_kernel<<<nblk, 256, LG_SMEM_BYTES>>>(Wlin, blin, out);
}

// round 10
// speedup vs baseline: 1.3545x; 1.2723x over previous
#include <cuda_runtime.h>
#include <cstdint>

#define VOCAB 50257
#define EMBED 128
#define BATCH 64
#define NSENT 50
#define TC 20
#define TQ 20
#define NHOPS 3

// Scratch (device global — no allocation allowed)
__device__ float g_u[BATCH * EMBED];
__device__ float g_m[BATCH * NSENT * EMBED];
__device__ float g_c[BATCH * NSENT * EMBED];

// ---------------------------------------------------------------------------
// Kernel 1: embedding sums. TWO warps per sentence (m-warp / c-warp).
// ---------------------------------------------------------------------------
__global__ void __launch_bounds__(128) embed_kernel(
        const int* __restrict__ stories,
        const int* __restrict__ questions,
        const int* __restrict__ masks,
        const float* __restrict__ WA,
        const float* __restrict__ WB,
        const float* __restrict__ WC,
        const float* __restrict__ WAT,
        const float* __restrict__ WCT) {
    int gwarp = (blockIdx.x * blockDim.x + threadIdx.x) >> 5;
    int lane = threadIdx.x & 31;

    if (gwarp < 2 * BATCH * NSENT) {
        int sent = gwarp >> 1;
        int half = gwarp & 1;
        int s = sent % NSENT;
        int mytok = (lane < TC) ? stories[sent * TC + lane] : 0;
        int mymsk = (lane < TC) ? masks[sent * TC + lane] : 1;
        unsigned ball = __ballot_sync(0xffffffffu, (lane < TC) && (mymsk == 0));
        int te = (ball != 0u) ? (s + 1) : 0;

        const float* tbl = half ? WC : WA;
        const float* ttbl = half ? WCT : WAT;
        float4 acc = *(const float4*)&ttbl[te * EMBED + lane * 4];
#pragma unroll
        for (int t = 0; t < TC; t++) {
            int tk = __shfl_sync(0xffffffffu, mytok, t);
            float4 a = *(const float4*)&tbl[(size_t)tk * EMBED + lane * 4];
            acc.x += a.x; acc.y += a.y; acc.z += a.z; acc.w += a.w;
        }
        float* dst = half ? g_c : g_m;
        *(float4*)&dst[(size_t)sent * EMBED + lane * 4] = acc;
    } else if (gwarp < 2 * BATCH * NSENT + BATCH) {
        int b = gwarp - 2 * BATCH * NSENT;
        int myq = (lane < TQ) ? questions[b * TQ + lane] : 0;
        float4 u = make_float4(0.f, 0.f, 0.f, 0.f);
#pragma unroll
        for (int t = 0; t < TQ; t++) {
            int tk = __shfl_sync(0xffffffffu, myq, t);
            float4 a = *(const float4*)&WB[(size_t)tk * EMBED + lane * 4];
            u.x += a.x; u.y += a.y; u.z += a.z; u.w += a.w;
        }
        *(float4*)&g_u[b * EMBED + lane * 4] = u;
    }
}

// ---------------------------------------------------------------------------
// Kernel 2: hops with full smem residency. One block per batch, 256 threads.
// m,c staged coalesced into dynamic smem once; 3 hops entirely from smem.
// ---------------------------------------------------------------------------
#define HOPS_SMEM ((2 * NSENT * EMBED + EMBED + 64) * 4)

__global__ void __launch_bounds__(256) hops_kernel() {
    extern __shared__ float hs[];
    float* m_s = hs;                       // 50*128
    float* c_s = hs + NSENT * EMBED;       // 50*128
    float* u_s = hs + 2 * NSENT * EMBED;   // 128
    float* sc = u_s + EMBED;               // 64

    int b = blockIdx.x;
    int tid = threadIdx.x;
    int w = tid >> 5, lane = tid & 31;

    // stage m, c (contiguous per batch), u
    const float4* gm = (const float4*)&g_m[(size_t)b * NSENT * EMBED];
    const float4* gc = (const float4*)&g_c[(size_t)b * NSENT * EMBED];
#pragma unroll
    for (int i = 0; i < 7; i++) {
        int q = tid + 256 * i;
        if (q < NSENT * EMBED / 4) {
            ((float4*)m_s)[q] = gm[q];
            ((float4*)c_s)[q] = gc[q];
        }
    }
    if (tid < EMBED) u_s[tid] = g_u[b * EMBED + tid];
    __syncthreads();

    for (int hop = 0; hop < NHOPS; hop++) {
        float4 uv = *(const float4*)&u_s[lane * 4];
        for (int n = w; n < NSENT; n += 8) {
            float4 mv = *(const float4*)&m_s[n * EMBED + lane * 4];
            float p = mv.x * uv.x + mv.y * uv.y + mv.z * uv.z + mv.w * uv.w;
#pragma unroll
            for (int o = 16; o > 0; o >>= 1) p += __shfl_xor_sync(0xffffffffu, p, o);
            if (lane == 0) sc[n] = p;
        }
        __syncthreads();
        if (w == 0) {
            float v0 = (lane < NSENT) ? sc[lane] : -1e30f;
            float v1 = (lane + 32 < NSENT) ? sc[lane + 32] : -1e30f;
            float mx = fmaxf(v0, v1);
#pragma unroll
            for (int o = 16; o > 0; o >>= 1) mx = fmaxf(mx, __shfl_xor_sync(0xffffffffu, mx, o));
            float e0 = (lane < NSENT) ? expf(v0 - mx) : 0.f;
            float e1 = (lane + 32 < NSENT) ? expf(v1 - mx) : 0.f;
            float s = e0 + e1;
#pragma unroll
            for (int o = 16; o > 0; o >>= 1) s += __shfl_xor_sync(0xffffffffu, s, o);
            float inv = 1.f / s;
            if (lane < NSENT) sc[lane] = e0 * inv;
            if (lane + 32 < NSENT) sc[lane + 32] = e1 * inv;
        }
        __syncthreads();
        if (tid < EMBED) {
            float o_acc = 0.f;
#pragma unroll 10
            for (int n = 0; n < NSENT; n++)
                o_acc += c_s[n * EMBED + tid] * sc[n];
            u_s[tid] += o_acc;
        }
        __syncthreads();
    }
    if (tid < EMBED) g_u[b * EMBED + tid] = u_s[tid];
}

// ---------------------------------------------------------------------------
// Kernel 3: logits via tf32 mma.sync, persistent CTAs + cp.async double buffer.
// Grid 148; CTA handles tiles bid, bid+148, bid+296 (128 vocab rows each).
// smem: us[64][132] (tf32) + wbuf[2][128][132] (raw fp32 via cp.async).
// While tile j computes, tile j+1 streams from DRAM.
// ---------------------------------------------------------------------------
__device__ __forceinline__ uint32_t tf32b(float x) {
    float r;
    asm("cvt.rna.tf32.f32 %0, %1;" : "=f"(r) : "f"(x));
    return __float_as_uint(r);
}
__device__ __forceinline__ void mma_tf32(float* c, const uint32_t* a,
                                         uint32_t b0, uint32_t b1) {
    asm volatile(
        "mma.sync.aligned.m16n8k8.row.col.f32.tf32.tf32.f32 "
        "{%0,%1,%2,%3}, {%4,%5,%6,%7}, {%8,%9}, {%0,%1,%2,%3};"
        : "+f"(c[0]), "+f"(c[1]), "+f"(c[2]), "+f"(c[3])
        : "r"(a[0]), "r"(a[1]), "r"(a[2]), "r"(a[3]), "r"(b0), "r"(b1));
}
__device__ __forceinline__ uint32_t sm_u32(const void* p) {
    uint32_t a;
    asm("{ .reg .u64 t; cvta.to.shared.u64 t, %1; cvt.u32.u64 %0, t; }"
        : "=r"(a) : "l"(p));
    return a;
}
__device__ __forceinline__ void cp_async16(uint32_t dst, const void* src) {
    asm volatile("cp.async.ca.shared.global [%0], [%1], 16;"
                 :: "r"(dst), "l"(src) : "memory");
}

#define LPAD 132
#define NTILES 393
#define LG_GRID 148
#define LG_SMEM_BYTES ((64 + 2 * 128) * LPAD * 4)

__global__ void __launch_bounds__(256) logits_mma_kernel(
        const float* __restrict__ W,
        const float* __restrict__ bias,
        float* __restrict__ out) {
    extern __shared__ uint32_t sh[];
    uint32_t (*us)[LPAD] = (uint32_t(*)[LPAD])sh;                 // 64 rows tf32
    float* wbuf[2];
    wbuf[0] = (float*)(sh + 64 * LPAD);                           // 128 rows fp32
    wbuf[1] = (float*)(sh + (64 + 128) * LPAD);

    int tid = threadIdx.x;
    int wid = tid >> 5, lane = tid & 31;
    int gid = lane >> 2, tig = lane & 3;
    int bid = blockIdx.x;

    // ---- stage u -> tf32 smem (64 x 128) ----
#pragma unroll
    for (int i = 0; i < 8; i++) {
        int q = tid + 256 * i;
        int row = q >> 5, kq = q & 31;
        float4 v = *(const float4*)(g_u + row * EMBED + kq * 4);
        us[row][kq * 4 + 0] = tf32b(v.x);
        us[row][kq * 4 + 1] = tf32b(v.y);
        us[row][kq * 4 + 2] = tf32b(v.z);
        us[row][kq * 4 + 3] = tf32b(v.w);
    }

    // ---- prefetch helper: issue one (possibly empty) cp.async group ----
    auto prefetch = [&](int j) {
        int tile = bid + LG_GRID * j;
        if (tile < NTILES) {
            int row0 = tile * 128;
            uint32_t base = sm_u32(wbuf[j & 1]);
#pragma unroll
            for (int i = 0; i < 16; i++) {
                int q = tid + 256 * i;
                int row = q >> 5, kq = q & 31;
                int grow = row0 + row;
                if (grow > VOCAB - 1) grow = VOCAB - 1;
                cp_async16(base + (uint32_t)(row * LPAD + kq * 4) * 4,
                           W + (size_t)grow * EMBED + kq * 4);
            }
        }
        asm volatile("cp.async.commit_group;" ::: "memory");
    };

    prefetch(0);
    prefetch(1);

    int rl = wid * 16 + gid;
    int rh = rl + 8;

    for (int j = 0; j < 3; j++) {
        int tile = bid + LG_GRID * j;
        if (tile >= NTILES) break;
        asm volatile("cp.async.wait_group 1;" ::: "memory");
        __syncthreads();

        const float* ws = wbuf[j & 1];
        float acc[8][4];
#pragma unroll
        for (int jj = 0; jj < 8; jj++)
#pragma unroll
            for (int q = 0; q < 4; q++) acc[jj][q] = 0.f;

#pragma unroll
        for (int s = 0; s < 16; s++) {
            int k0 = s * 8 + tig;
            uint32_t a[4];
            a[0] = tf32b(ws[rl * LPAD + k0]);
            a[1] = tf32b(ws[rh * LPAD + k0]);
            a[2] = tf32b(ws[rl * LPAD + k0 + 4]);
            a[3] = tf32b(ws[rh * LPAD + k0 + 4]);
#pragma unroll
            for (int jj = 0; jj < 8; jj++) {
                uint32_t b0 = us[jj * 8 + gid][k0];
                uint32_t b1 = us[jj * 8 + gid][k0 + 4];
                mma_tf32(acc[jj], a, b0, b1);
            }
        }

        // epilogue for this tile
        int row0 = tile * 128;
        int r_lo = row0 + rl;
        int r_hi = row0 + rh;
        bool vlo = (r_lo < VOCAB), vhi = (r_hi < VOCAB);
        float blo = vlo ? __ldg(bias + r_lo) : 0.f;
        float bhi = vhi ? __ldg(bias + r_hi) : 0.f;
#pragma unroll
        for (int jj = 0; jj < 8; jj++) {
            int n0 = jj * 8 + 2 * tig;
            int n1 = n0 + 1;
            if (vlo) {
                out[(size_t)n0 * VOCAB + r_lo] = acc[jj][0] + blo;
                out[(size_t)n1 * VOCAB + r_lo] = acc[jj][1] + blo;
            }
            if (vhi) {
                out[(size_t)n0 * VOCAB + r_hi] = acc[jj][2] + bhi;
                out[(size_t)n1 * VOCAB + r_hi] = acc[jj][3] + bhi;
            }
        }

        __syncthreads();      // all warps done reading wbuf[j&1]
        prefetch(j + 2);      // refill it for tile j+2 (empty group if none)
    }
}

extern "C" void kernel_launch(void* const* d_in, const int* in_sizes, int n_in,
                              void* d_out, int out_size) {
    const int* stories = (const int*)d_in[0];
    const int* questions = (const int*)d_in[1];
    const int* masks = (const int*)d_in[2];
    const float* WA = (const float*)d_in[3];
    const float* WB = (const float*)d_in[4];
    const float* WC = (const float*)d_in[5];
    const float* WAT = (const float*)d_in[6];
    const float* WCT = (const float*)d_in[7];
    const float* Wlin = (const float*)d_in[8];
    const float* blin = (const float*)d_in[9];
    float* out = (float*)d_out;

    int total_warps = 2 * BATCH * NSENT + BATCH;
    int embed_blocks = (total_warps * 32 + 127) / 128;
    embed_kernel<<<embed_blocks, 128>>>(stories, questions, masks, WA, WB, WC, WAT, WCT);

    cudaFuncSetAttribute(hops_kernel, cudaFuncAttributeMaxDynamicSharedMemorySize,
                         HOPS_SMEM);
    hops_kernel<<<BATCH, 256, HOPS_SMEM>>>();

    cudaFuncSetAttribute(logits_mma_kernel,
                         cudaFuncAttributeMaxDynamicSharedMemorySize, LG_SMEM_BYTES);
    logits_mma_kernel<<<LG_GRID, 256, LG_SMEM_BYTES>>>(Wlin, blin, out);
}